// round 13
// baseline (speedup 1.0000x reference)
#include <cuda_runtime.h>
#include <cuda_bf16.h>
#include <float.h>

#define NEXP 64
#define TPB  256

// Rare exact path: faithful reproduction of the reference fp32 sequence
// (sqrt logits + softmax-tie band). __noinline__ + partial unroll so it never
// inflates the main kernel's register count (R3/R10 lesson).
__device__ __noinline__ int exact_argmax(float px, float py, float pz,
                                         const float4* __restrict__ sc)
{
    float m = -FLT_MAX;
    #pragma unroll 4
    for (int e = 0; e < NEXP; e++) {
        float4 c = sc[e];
        float dx = __fsub_rn(px, c.x);
        float dy = __fsub_rn(py, c.y);
        float dz = __fsub_rn(pz, c.z);
        float d2 = __fadd_rn(__fadd_rn(__fmul_rn(dx, dx), __fmul_rn(dy, dy)),
                             __fmul_rn(dz, dz));
        float dist = __fsqrt_rn(__fadd_rn(d2, 1e-12f));
        float li   = __fmul_rn(10.0f, __fsub_rn(c.w, dist));
        if (li > m) m = li;
    }
    // softmax tie band: exp(l-m) rounds to 1.0f when (m-l) <= 2^-25, so
    // argmax(softmax) picks the FIRST index inside that band.
    const float band = 2.9802322e-8f;  // 2^-25
    #pragma unroll 4
    for (int e = 0; e < NEXP; e++) {
        float4 c = sc[e];
        float dx = __fsub_rn(px, c.x);
        float dy = __fsub_rn(py, c.y);
        float dz = __fsub_rn(pz, c.z);
        float d2 = __fadd_rn(__fadd_rn(__fmul_rn(dx, dx), __fmul_rn(dy, dy)),
                             __fmul_rn(dz, dz));
        float dist = __fsqrt_rn(__fadd_rn(d2, 1e-12f));
        float li   = __fmul_rn(10.0f, __fsub_rn(c.w, dist));
        if (__fsub_rn(m, li) <= band) return e;
    }
    return NEXP - 1;  // unreachable
}

__global__ void __launch_bounds__(TPB, 8)
optix_route_fused(const float* __restrict__ pos,
                  const float* __restrict__ centers,
                  const float* __restrict__ radii,
                  float* __restrict__ out_probs,
                  float* __restrict__ out_ids,
                  int B, int write_ids)
{
    __shared__ float4 sc[NEXP];      // (cx, cy, cz, safe_r)
    __shared__ int    s_uniform;

    const int tid  = threadIdx.x;
    const int lane = tid & 31;
    const int wid  = tid >> 5;

    if (tid < NEXP) {
        float cx = centers[3 * tid + 0];
        float cy = centers[3 * tid + 1];
        float cz = centers[3 * tid + 2];
        float r  = fmaxf(fabsf(radii[tid]), 0.01f);
        sc[tid] = make_float4(cx, cy, cz, r);
    }
    __syncthreads();
    if (tid == 0) {
        float r0 = sc[0].w;
        int u = 1;
        #pragma unroll
        for (int e = 1; e < NEXP; e++) u &= (sc[e].w == r0);
        s_uniform = u;
    }
    __syncthreads();   // the ONLY block barrier
    const int uniform = s_uniform;

    // This warp owns output rows [warprow, warprow+32); my row is gpos.
    const long long warprow = (long long)blockIdx.x * TPB + wid * 32;
    const long long gpos    = warprow + lane;
    const long long lpos    = (gpos < B) ? gpos : (long long)(B - 1);

    const float px = pos[3 * lpos + 0];
    const float py = pos[3 * lpos + 1];
    const float pz = pos[3 * lpos + 2];

    float4* __restrict__ wp = (float4*)out_probs + warprow * 16 + lane;
    const bool fullwarp = (warprow + 32 <= B);
    const int  rsel     = lane >> 4;
    const float4 zero4  = make_float4(0.f, 0.f, 0.f, 0.f);

    // ---- phase 1: argmax (R7's proven math) with zero-fill interleaved ----
    // One independent zero STG.128 per 4 experts: the 256MB store stream flows
    // and overlaps the compute instead of queueing after it, naturally paced.
    float best = FLT_MAX, best2 = FLT_MAX;
    int   id = 0;
    #pragma unroll
    for (int g = 0; g < 16; g++) {
        #pragma unroll
        for (int q = 0; q < 4; q++) {
            int e = g * 4 + q;
            float4 c = sc[e];
            float dx = px - c.x;
            float dy = py - c.y;
            float dz = pz - c.z;
            float d2 = __fmaf_rn(dx, dx, __fmaf_rn(dy, dy, dz * dz));
            float mx = fmaxf(best, d2);
            best2 = fminf(best2, mx);
            id    = (d2 < best) ? e : id;
            best  = fminf(best, d2);
        }
        if (fullwarp) {
            wp[g * 32] = zero4;
        } else if (warprow + 2 * g + rsel < B) {
            wp[g * 32] = zero4;
        }
    }

    if (gpos < B) {
        // uniform radii => logit order == reverse d2 order; FMA deviation
        // (<~2.4e-7 rel) absorbed by the proven tight margin (R8 lesson:
        // wide margin = warp divergence death).
        bool need_exact = (!uniform) ||
                          (best2 - best <= __fmaf_rn(best, 2e-6f, 1e-9f));
        if (need_exact) id = exact_argmax(px, py, pz, sc);
    }

    // Warp-scope ordering: my row's zeros were all written by THIS warp.
    __syncwarp();

    // ---- phase 2: one scalar hot store per row (+ ids) ----
    if (gpos < B) {
        out_probs[gpos * NEXP + id] = 1.0f;
        if (write_ids) out_ids[gpos] = (float)id;
    }
}

extern "C" void kernel_launch(void* const* d_in, const int* in_sizes, int n_in,
                              void* d_out, int out_size)
{
    const float* pos     = (const float*)d_in[0];   // positions_3d (B,3)
    const float* centers = (const float*)d_in[1];   // centers (64,3)
    const float* radii   = (const float*)d_in[2];   // radii (64,)

    int B = in_sizes[0] / 3;
    float* out_probs = (float*)d_out;
    long long need_ids = (long long)B * (NEXP + 1);
    int write_ids = ((long long)out_size >= need_ids) ? 1 : 0;
    float* out_ids = out_probs + (long long)B * NEXP;

    int grid = (B + TPB - 1) / TPB;
    optix_route_fused<<<grid, TPB>>>(pos, centers, radii, out_probs, out_ids, B, write_ids);
}